// round 1
// baseline (speedup 1.0000x reference)
#include <cuda_runtime.h>

#define N_TREES     15
#define DEPTH       3
#define INPUT_DIM   128
#define N_CLASSES   10
#define N_LEAVES    8
#define N_INTERNAL  7
#define PER_TREE    (N_INTERNAL*INPUT_DIM + N_INTERNAL + N_LEAVES*N_CLASSES)  // 983
#define NODES       (N_TREES*N_INTERNAL)   // 105
#define BLOCK       256

// dynamic smem layout (floats):
//   Wsm[NODES*INPUT_DIM]   = 13440
//   bsm[NODES]             = 105
//   Msm[N_TREES*N_LEAVES*N_CLASSES] = 1200
#define SMEM_FLOATS (NODES*INPUT_DIM + NODES + N_TREES*N_LEAVES*N_CLASSES)

__global__ __launch_bounds__(BLOCK)
void sdt_ensemble_kernel(const float* __restrict__ x,
                         const float* __restrict__ params,
                         float* __restrict__ out,
                         int batch)
{
    extern __shared__ float smem[];
    float* Wsm = smem;                         // [105][128]
    float* bsm = Wsm + NODES*INPUT_DIM;        // [105]
    float* Msm = bsm + NODES;                  // [15][8][10]

    const int tid = threadIdx.x;

    // ---- Stage weights into smem ----
    for (int j = tid; j < NODES*INPUT_DIM; j += BLOCK) {
        int t = j / (N_INTERNAL*INPUT_DIM);
        int r = j - t*(N_INTERNAL*INPUT_DIM);
        Wsm[j] = params[t*PER_TREE + r];
    }
    for (int j = tid; j < NODES; j += BLOCK) {
        int t = j / N_INTERNAL;
        int n = j - t*N_INTERNAL;
        bsm[j] = params[t*PER_TREE + N_INTERNAL*INPUT_DIM + n];
    }
    // ---- Precompute M[t][l][c] = softmax(tree_w)[t] * softmax(leaf_logits[t][l])[c] ----
    if (tid < N_TREES*N_LEAVES) {
        int t = tid / N_LEAVES;
        int l = tid - t*N_LEAVES;
        const float* twl = params + N_TREES*PER_TREE;
        float mx = twl[0];
        #pragma unroll
        for (int i = 1; i < N_TREES; ++i) mx = fmaxf(mx, twl[i]);
        float s = 0.f;
        #pragma unroll
        for (int i = 0; i < N_TREES; ++i) s += __expf(twl[i] - mx);
        float tw = __expf(twl[t] - mx) / s;

        const float* ll = params + t*PER_TREE + N_INTERNAL*INPUT_DIM + N_INTERNAL
                        + l*N_CLASSES;
        float m2 = ll[0];
        #pragma unroll
        for (int c = 1; c < N_CLASSES; ++c) m2 = fmaxf(m2, ll[c]);
        float e[N_CLASSES];
        float s2 = 0.f;
        #pragma unroll
        for (int c = 0; c < N_CLASSES; ++c) { e[c] = __expf(ll[c] - m2); s2 += e[c]; }
        float inv = tw / s2;
        #pragma unroll
        for (int c = 0; c < N_CLASSES; ++c)
            Msm[(t*N_LEAVES + l)*N_CLASSES + c] = e[c] * inv;
    }
    __syncthreads();

    const long long b = (long long)blockIdx.x * BLOCK + tid;
    if (b >= batch) return;

    // ---- Main GEMV: z[n] = b[n] + sum_k x[b,k] * W[n,k] ----
    const float4* xv = reinterpret_cast<const float4*>(x) + b*(INPUT_DIM/4);

    float z[NODES];
    #pragma unroll
    for (int n = 0; n < NODES; ++n) z[n] = bsm[n];

    #pragma unroll 1
    for (int k4 = 0; k4 < INPUT_DIM/4; ++k4) {
        const float4 xx = xv[k4];
        const float4* wp = reinterpret_cast<const float4*>(Wsm) + k4;
        #pragma unroll
        for (int n = 0; n < NODES; ++n) {
            const float4 w = wp[n*(INPUT_DIM/4)];
            z[n] = fmaf(xx.x, w.x,
                   fmaf(xx.y, w.y,
                   fmaf(xx.z, w.z,
                   fmaf(xx.w, w.w, z[n]))));
        }
    }

    // ---- Epilogue: sigmoid -> leaf path probs -> class mixture ----
    float acc[N_CLASSES];
    #pragma unroll
    for (int c = 0; c < N_CLASSES; ++c) acc[c] = 0.f;

    #pragma unroll
    for (int t = 0; t < N_TREES; ++t) {
        float p[N_INTERNAL], q[N_INTERNAL];
        #pragma unroll
        for (int n = 0; n < N_INTERNAL; ++n) {
            float e  = __expf(-z[t*N_INTERNAL + n]);
            float pp = 1.f / (1.f + e);   // sigmoid(z)  -> right-branch prob
            p[n] = pp;
            q[n] = e * pp;                // sigmoid(-z) -> left-branch prob (no cancellation)
        }
        float tp[N_LEAVES];
        #pragma unroll
        for (int l = 0; l < N_LEAVES; ++l) {
            int node = l + N_INTERNAL;
            float prob = 1.f;
            #pragma unroll
            for (int d = 0; d < DEPTH; ++d) {
                int par = (node - 1) >> 1;
                prob *= (node & 1) ? q[par] : p[par];   // even child = Right = p
                node = par;
            }
            tp[l] = prob;
        }
        const float* Mt = Msm + t*N_LEAVES*N_CLASSES;
        #pragma unroll
        for (int l = 0; l < N_LEAVES; ++l) {
            #pragma unroll
            for (int c = 0; c < N_CLASSES; ++c)
                acc[c] = fmaf(tp[l], Mt[l*N_CLASSES + c], acc[c]);
        }
    }

    float* o = out + b*N_CLASSES;
    #pragma unroll
    for (int c = 0; c < N_CLASSES; ++c) o[c] = acc[c];
}

extern "C" void kernel_launch(void* const* d_in, const int* in_sizes, int n_in,
                              void* d_out, int out_size)
{
    const float* x      = (const float*)d_in[0];
    const float* params = (const float*)d_in[1];
    float* out          = (float*)d_out;

    int batch = in_sizes[0] / INPUT_DIM;

    size_t smem_bytes = SMEM_FLOATS * sizeof(float);  // 58,980 B
    cudaFuncSetAttribute(sdt_ensemble_kernel,
                         cudaFuncAttributeMaxDynamicSharedMemorySize,
                         (int)smem_bytes);

    int grid = (batch + BLOCK - 1) / BLOCK;
    sdt_ensemble_kernel<<<grid, BLOCK, smem_bytes>>>(x, params, out, batch);
}

// round 2
// speedup vs baseline: 1.1538x; 1.1538x over previous
#include <cuda_runtime.h>

#define N_TREES     15
#define DEPTH       3
#define INPUT_DIM   128
#define N_CLASSES   10
#define N_LEAVES    8
#define N_INTERNAL  7
#define PER_TREE    (N_INTERNAL*INPUT_DIM + N_INTERNAL + N_LEAVES*N_CLASSES)  // 983
#define NODES       (N_TREES*N_INTERNAL)   // 105
#define NPAIR       53                      // ceil(105/2), node 105 zero-padded
#define BLOCK       128

// dynamic smem layout (floats):
//   Wp  [NPAIR*64*4]  = 13568   (pair-interleaved: [(p*64+k2)*4 + slot])
//   bp  [NPAIR*2]     = 106     (bias pairs)
//   Msm [15*8*10]     = 1200
#define WP_FLOATS   (NPAIR*64*4)
#define BP_OFF      WP_FLOATS
#define M_OFF       (BP_OFF + NPAIR*2)
#define SMEM_FLOATS (M_OFF + N_TREES*N_LEAVES*N_CLASSES)

typedef unsigned long long ull;

#define FMA2(acc, a, b) \
    asm("fma.rn.f32x2 %0, %1, %2, %0;" : "+l"(acc) : "l"(a), "l"(b))

__device__ __forceinline__ ull pack2(float lo, float hi) {
    ull r; asm("mov.b64 %0, {%1, %2};" : "=l"(r) : "f"(lo), "f"(hi)); return r;
}
__device__ __forceinline__ void unpack2(ull v, float& lo, float& hi) {
    asm("mov.b64 {%0, %1}, %2;" : "=f"(lo), "=f"(hi) : "l"(v));
}

__global__ __launch_bounds__(BLOCK, 3)
void sdt_ensemble_kernel(const float* __restrict__ x,
                         const float* __restrict__ params,
                         float* __restrict__ out,
                         int batch)
{
    extern __shared__ float smem[];
    float* Wp  = smem;
    float* bp  = smem + BP_OFF;
    float* Msm = smem + M_OFF;

    const int tid = threadIdx.x;

    // ---- Stage pair-interleaved weights into smem ----
    // float index j = (p*64 + k2)*4 + slot
    //   node = 2p + (slot&1),  k = 2*k2 + (slot>>1)
    for (int j = tid; j < WP_FLOATS; j += BLOCK) {
        int slot = j & 3;
        int idx4 = j >> 2;
        int p    = idx4 >> 6;
        int k2   = idx4 & 63;
        int node = 2*p + (slot & 1);
        int k    = 2*k2 + (slot >> 1);
        float v = 0.f;
        if (node < NODES) {
            int t = node / N_INTERNAL;
            int n = node - t*N_INTERNAL;
            v = params[t*PER_TREE + n*INPUT_DIM + k];
        }
        Wp[j] = v;
    }
    // bias pairs
    for (int j = tid; j < NPAIR*2; j += BLOCK) {
        float v = 0.f;
        if (j < NODES) {
            int t = j / N_INTERNAL;
            int n = j - t*N_INTERNAL;
            v = params[t*PER_TREE + N_INTERNAL*INPUT_DIM + n];
        }
        bp[j] = v;
    }
    // ---- Precompute M[t][l][c] = softmax(tree_w)[t] * softmax(leaf_logits[t][l])[c] ----
    if (tid < N_TREES*N_LEAVES) {
        int t = tid / N_LEAVES;
        int l = tid - t*N_LEAVES;
        const float* twl = params + N_TREES*PER_TREE;
        float mx = twl[0];
        #pragma unroll
        for (int i = 1; i < N_TREES; ++i) mx = fmaxf(mx, twl[i]);
        float s = 0.f;
        #pragma unroll
        for (int i = 0; i < N_TREES; ++i) s += __expf(twl[i] - mx);
        float tw = __expf(twl[t] - mx) / s;

        const float* ll = params + t*PER_TREE + N_INTERNAL*INPUT_DIM + N_INTERNAL
                        + l*N_CLASSES;
        float m2 = ll[0];
        #pragma unroll
        for (int c = 1; c < N_CLASSES; ++c) m2 = fmaxf(m2, ll[c]);
        float e[N_CLASSES];
        float s2 = 0.f;
        #pragma unroll
        for (int c = 0; c < N_CLASSES; ++c) { e[c] = __expf(ll[c] - m2); s2 += e[c]; }
        float inv = tw / s2;
        #pragma unroll
        for (int c = 0; c < N_CLASSES; ++c)
            Msm[(t*N_LEAVES + l)*N_CLASSES + c] = e[c] * inv;
    }
    __syncthreads();

    const long long b = (long long)blockIdx.x * BLOCK + tid;
    if (b >= batch) return;

    // ---- Main GEMV with packed f32x2 FFMA over node pairs ----
    ull zac[NPAIR];
    {
        const ull* bpu = reinterpret_cast<const ull*>(bp);
        #pragma unroll
        for (int p = 0; p < NPAIR; ++p) zac[p] = bpu[p];
    }

    const float4* xv = reinterpret_cast<const float4*>(x) + b*(INPUT_DIM/4);
    const ulonglong2* WU = reinterpret_cast<const ulonglong2*>(Wp);

    #pragma unroll 1
    for (int k4 = 0; k4 < INPUT_DIM/4; ++k4) {
        const float4 xx = xv[k4];
        const ull xa = pack2(xx.x, xx.x);
        const ull xb = pack2(xx.y, xx.y);
        const ull xc = pack2(xx.z, xx.z);
        const ull xd = pack2(xx.w, xx.w);
        const ulonglong2* wrow = WU + 2*k4;
        #pragma unroll
        for (int p = 0; p < NPAIR; ++p) {
            const ulonglong2 wA = wrow[p*64];      // k = 4k4, 4k4+1
            const ulonglong2 wB = wrow[p*64 + 1];  // k = 4k4+2, 4k4+3
            FMA2(zac[p], xa, wA.x);
            FMA2(zac[p], xb, wA.y);
            FMA2(zac[p], xc, wB.x);
            FMA2(zac[p], xd, wB.y);
        }
    }

    // ---- Unpack z ----
    float z[NPAIR*2];
    #pragma unroll
    for (int p = 0; p < NPAIR; ++p) unpack2(zac[p], z[2*p], z[2*p+1]);

    // ---- Epilogue: sigmoid -> leaf path probs -> class mixture ----
    float acc[N_CLASSES];
    #pragma unroll
    for (int c = 0; c < N_CLASSES; ++c) acc[c] = 0.f;

    #pragma unroll
    for (int t = 0; t < N_TREES; ++t) {
        float p_[N_INTERNAL], q_[N_INTERNAL];
        #pragma unroll
        for (int n = 0; n < N_INTERNAL; ++n) {
            float e  = __expf(-z[t*N_INTERNAL + n]);
            float pp = 1.f / (1.f + e);   // sigmoid(z)  -> right-branch prob
            p_[n] = pp;
            q_[n] = e * pp;               // sigmoid(-z) -> left-branch prob
        }
        float tp[N_LEAVES];
        #pragma unroll
        for (int l = 0; l < N_LEAVES; ++l) {
            int node = l + N_INTERNAL;
            float prob = 1.f;
            #pragma unroll
            for (int d = 0; d < DEPTH; ++d) {
                int par = (node - 1) >> 1;
                prob *= (node & 1) ? q_[par] : p_[par];
                node = par;
            }
            tp[l] = prob;
        }
        const float* Mt = Msm + t*N_LEAVES*N_CLASSES;
        #pragma unroll
        for (int l = 0; l < N_LEAVES; ++l) {
            #pragma unroll
            for (int c = 0; c < N_CLASSES; ++c)
                acc[c] = fmaf(tp[l], Mt[l*N_CLASSES + c], acc[c]);
        }
    }

    float* o = out + b*N_CLASSES;
    #pragma unroll
    for (int c = 0; c < N_CLASSES; ++c) o[c] = acc[c];
}

extern "C" void kernel_launch(void* const* d_in, const int* in_sizes, int n_in,
                              void* d_out, int out_size)
{
    const float* x      = (const float*)d_in[0];
    const float* params = (const float*)d_in[1];
    float* out          = (float*)d_out;

    int batch = in_sizes[0] / INPUT_DIM;

    size_t smem_bytes = SMEM_FLOATS * sizeof(float);  // 59,496 B
    cudaFuncSetAttribute(sdt_ensemble_kernel,
                         cudaFuncAttributeMaxDynamicSharedMemorySize,
                         (int)smem_bytes);

    int grid = (batch + BLOCK - 1) / BLOCK;
    sdt_ensemble_kernel<<<grid, BLOCK, smem_bytes>>>(x, params, out, batch);
}